// round 5
// baseline (speedup 1.0000x reference)
#include <cuda_runtime.h>

#define NN 100000
#define EE 1600000
#define FDIM 128
#define OUTDIM 256

// ---------------- scratch (device globals; referenced directly by kernels) ---
__device__ int      g_deg[NN];
__device__ float    g_dinv[NN];
__device__ int      g_rowstart[NN + 1];
__device__ int      g_fill[NN];
__device__ int      g_srcSorted[EE];
__device__ int      g_bsum[128];
__device__ int      g_is64;
__device__ __align__(16) float g_h[(size_t)NN * FDIM];
__device__ __align__(16) float g_x[(size_t)NN * FDIM];
__device__ float    g_colsum[FDIM];
__device__ unsigned g_colmax[FDIM];

// ---------------- dtype sniff: int64-as-int32 has zero odd words -------------
__global__ void k_sniff(const int* __restrict__ ei32) {
    if (threadIdx.x == 0 && blockIdx.x == 0) {
        int any = 0;
        for (int i = 1; i < 1024; i += 2) any |= ei32[i];
        g_is64 = (any == 0) ? 1 : 0;
    }
}

__device__ __forceinline__ int clampN(int x) {
    if (x < 0) x = 0;
    if (x >= NN) x = NN - 1;
    return x;
}

__device__ __forceinline__ int loadIdx(const int* ei32, long long pos) {
    // pos in [0, 2*EE): logical element index into edge_index flat array
    if (g_is64) {
        // little-endian int64, values < 2^31: low word at 2*pos
        return clampN(ei32[2 * pos]);
    }
    return clampN(ei32[pos]);
}

// ---------------- setup kernels ----------------------------------------------
__global__ void __launch_bounds__(256) k_init() {
    int i = blockIdx.x * 256 + threadIdx.x;
    if (i < NN) g_deg[i] = 1;  // self loop
    if (i < FDIM) { g_colsum[i] = 0.f; g_colmax[i] = 0u; }
}

__global__ void __launch_bounds__(256) k_count(const int* __restrict__ ei32) {
    int e = blockIdx.x * 256 + threadIdx.x;
    if (e < EE) {
        int d = loadIdx(ei32, (long long)EE + e);
        atomicAdd(&g_deg[d], 1);
    }
}

__global__ void __launch_bounds__(256) k_dinv() {
    int i = blockIdx.x * 256 + threadIdx.x;
    if (i < NN) g_dinv[i] = rsqrtf((float)g_deg[i]);
}

// exclusive scan of (deg-1) over N: per-block (1024 elems) + block sums + add
__global__ void __launch_bounds__(256) k_scan1() {
    __shared__ int sh[256];
    int t = threadIdx.x;
    int base = blockIdx.x * 1024;
    int c[4]; int local = 0;
#pragma unroll
    for (int j = 0; j < 4; j++) {
        int i = base + t * 4 + j;
        c[j] = (i < NN) ? (g_deg[i] - 1) : 0;
        local += c[j];
    }
    sh[t] = local; __syncthreads();
#pragma unroll
    for (int off = 1; off < 256; off <<= 1) {
        int v = (t >= off) ? sh[t - off] : 0;
        __syncthreads();
        sh[t] += v;
        __syncthreads();
    }
    if (t == 255) g_bsum[blockIdx.x] = sh[255];
    int run = sh[t] - local;
#pragma unroll
    for (int j = 0; j < 4; j++) {
        int i = base + t * 4 + j;
        if (i < NN) g_rowstart[i] = run;
        run += c[j];
    }
}

__global__ void k_scan2(int nb) {
    if (threadIdx.x == 0 && blockIdx.x == 0) {
        int acc = 0;
        for (int b = 0; b < nb; b++) { int v = g_bsum[b]; g_bsum[b] = acc; acc += v; }
        g_rowstart[NN] = acc;
    }
}

__global__ void __launch_bounds__(256) k_scan3() {
    int i = blockIdx.x * 256 + threadIdx.x;
    if (i < NN) {
        int v = g_rowstart[i] + g_bsum[i >> 10];
        g_rowstart[i] = v;
        g_fill[i] = v;
    }
}

__global__ void __launch_bounds__(256) k_fill(const int* __restrict__ ei32) {
    int e = blockIdx.x * 256 + threadIdx.x;
    if (e < EE) {
        int s = loadIdx(ei32, e);
        int d = loadIdx(ei32, (long long)EE + e);
        int pos = atomicAdd(&g_fill[d], 1);
        if (pos >= 0 && pos < EE) g_srcSorted[pos] = s;
    }
}

// ---------------- dense transform: g_h = X @ W (fp32) ------------------------
// block = 256 thr = 8 warps; warp: 4 rows x 128 cols; thread: 4 rows x 4 cols.
__global__ void __launch_bounds__(256) k_gemm(const float* __restrict__ Xin,
                                              int useGX,
                                              const float* __restrict__ W) {
    const float* X = useGX ? (const float*)g_x : Xin;
    int cg = threadIdx.x & 31;
    int rg = threadIdx.x >> 5;
    int r0 = blockIdx.x * 32 + rg * 4;
    int c0 = cg * 4;
    const float* x0 = X + (size_t)r0 * FDIM;

    float4 acc0 = make_float4(0.f, 0.f, 0.f, 0.f);
    float4 acc1 = acc0, acc2 = acc0, acc3 = acc0;

#pragma unroll 4
    for (int k = 0; k < FDIM; k += 4) {
        float4 xa = __ldg((const float4*)(x0 + k));
        float4 xb = __ldg((const float4*)(x0 + FDIM + k));
        float4 xc = __ldg((const float4*)(x0 + 2 * FDIM + k));
        float4 xd = __ldg((const float4*)(x0 + 3 * FDIM + k));
#pragma unroll
        for (int j = 0; j < 4; j++) {
            float4 w = __ldg((const float4*)(W + (k + j) * FDIM + c0));
            float sa = (j == 0) ? xa.x : (j == 1) ? xa.y : (j == 2) ? xa.z : xa.w;
            float sb = (j == 0) ? xb.x : (j == 1) ? xb.y : (j == 2) ? xb.z : xb.w;
            float sc = (j == 0) ? xc.x : (j == 1) ? xc.y : (j == 2) ? xc.z : xc.w;
            float sd = (j == 0) ? xd.x : (j == 1) ? xd.y : (j == 2) ? xd.z : xd.w;
            acc0.x = fmaf(sa, w.x, acc0.x); acc0.y = fmaf(sa, w.y, acc0.y);
            acc0.z = fmaf(sa, w.z, acc0.z); acc0.w = fmaf(sa, w.w, acc0.w);
            acc1.x = fmaf(sb, w.x, acc1.x); acc1.y = fmaf(sb, w.y, acc1.y);
            acc1.z = fmaf(sb, w.z, acc1.z); acc1.w = fmaf(sb, w.w, acc1.w);
            acc2.x = fmaf(sc, w.x, acc2.x); acc2.y = fmaf(sc, w.y, acc2.y);
            acc2.z = fmaf(sc, w.z, acc2.z); acc2.w = fmaf(sc, w.w, acc2.w);
            acc3.x = fmaf(sd, w.x, acc3.x); acc3.y = fmaf(sd, w.y, acc3.y);
            acc3.z = fmaf(sd, w.z, acc3.z); acc3.w = fmaf(sd, w.w, acc3.w);
        }
    }
    float4* H4 = (float4*)g_h;
    H4[((size_t)r0 * FDIM + c0) >> 2]       = acc0;
    H4[((size_t)(r0 + 1) * FDIM + c0) >> 2] = acc1;
    H4[((size_t)(r0 + 2) * FDIM + c0) >> 2] = acc2;
    H4[((size_t)(r0 + 3) * FDIM + c0) >> 2] = acc3;
}

// ---------------- aggregation: g_x[i] = relu(sum_e norm*g_h[src] + dinv^2*g_h[i] + b)
__global__ void __launch_bounds__(256) k_agg(const float* __restrict__ bias) {
    int node = blockIdx.x * 8 + (threadIdx.x >> 5);
    int lane = threadIdx.x & 31;
    const float4* h4 = (const float4*)g_h;
    float di = g_dinv[node];
    float4 acc = __ldg(h4 + (size_t)node * 32 + lane);
    float sw = di * di;
    acc.x *= sw; acc.y *= sw; acc.z *= sw; acc.w *= sw;
    int e = g_rowstart[node], eend = g_rowstart[node + 1];
    for (; e < eend; ++e) {
        int s = __ldg(g_srcSorted + e);
        float w = __ldg(g_dinv + s) * di;
        float4 hv = __ldg(h4 + (size_t)s * 32 + lane);
        acc.x = fmaf(w, hv.x, acc.x);
        acc.y = fmaf(w, hv.y, acc.y);
        acc.z = fmaf(w, hv.z, acc.z);
        acc.w = fmaf(w, hv.w, acc.w);
    }
    float4 b = __ldg((const float4*)bias + lane);
    acc.x = fmaxf(acc.x + b.x, 0.f);
    acc.y = fmaxf(acc.y + b.y, 0.f);
    acc.z = fmaxf(acc.z + b.z, 0.f);
    acc.w = fmaxf(acc.w + b.w, 0.f);
    ((float4*)g_x)[(size_t)node * 32 + lane] = acc;
}

// ---------------- global mean + max pooling over rows of g_x -----------------
__global__ void __launch_bounds__(128) k_pool() {
    int c = threadIdx.x;
    int rbeg = blockIdx.x * 512;
    int rend = rbeg + 512; if (rend > NN) rend = NN;
    float s = 0.f, m = 0.f;  // post-relu values are >= 0
    for (int r = rbeg; r < rend; ++r) {
        float v = __ldg(&g_x[(size_t)r * FDIM + c]);
        s += v;
        m = fmaxf(m, v);
    }
    atomicAdd(&g_colsum[c], s);
    atomicMax(&g_colmax[c], __float_as_uint(m));
}

// ---------------- final FC: out = [mean||max] @ fcW + fcb --------------------
__global__ void __launch_bounds__(256) k_fc(const float* __restrict__ fcW,
                                            const float* __restrict__ fcb,
                                            float* __restrict__ out) {
    __shared__ float pooled[2 * FDIM];
    int t = threadIdx.x;
    if (t < FDIM) pooled[t] = g_colsum[t] * (1.0f / (float)NN);
    else          pooled[t] = __uint_as_float(g_colmax[t - FDIM]);
    __syncthreads();
    float a = fcb[t];
#pragma unroll 8
    for (int k = 0; k < 2 * FDIM; ++k)
        a = fmaf(pooled[k], __ldg(fcW + k * OUTDIM + t), a);
    out[t] = a;
}

// -----------------------------------------------------------------------------
extern "C" void kernel_launch(void* const* d_in, const int* in_sizes, int n_in,
                              void* d_out, int out_size) {
    // Robust input binding: resolve by element count (all counts distinct except
    // W1/W2 and b1/b2, which keep their relative order). Positional fallback.
    const float* X = 0; const int* ei = 0;
    const float *W1 = 0, *b1 = 0, *W2 = 0, *b2 = 0, *fcW = 0, *fcb = 0;
    for (int i = 0; i < n_in; i++) {
        long long sz = in_sizes[i];
        const void* p = d_in[i];
        if      (sz == (long long)NN * FDIM)      X = (const float*)p;
        else if (sz == 2LL * EE)                  ei = (const int*)p;
        else if (sz == (long long)FDIM * FDIM)  { if (!W1) W1 = (const float*)p; else W2 = (const float*)p; }
        else if (sz == FDIM)                    { if (!b1) b1 = (const float*)p; else b2 = (const float*)p; }
        else if (sz == 2LL * FDIM * OUTDIM)       fcW = (const float*)p;
        else if (sz == OUTDIM)                    fcb = (const float*)p;
    }
    if (!X || !ei || !W1 || !b1 || !W2 || !b2 || !fcW || !fcb) {
        X   = (const float*)d_in[0];
        ei  = (const int*)d_in[1];
        W1  = (const float*)d_in[2];
        b1  = (const float*)d_in[3];
        W2  = (const float*)d_in[4];
        b2  = (const float*)d_in[5];
        fcW = (const float*)d_in[6];
        fcb = (const float*)d_in[7];
    }
    float* out = (float*)d_out;

    const int nb = (NN + 1023) / 1024;  // 98 scan blocks

    // graph structure (rebuilt each call; deterministic work)
    k_sniff<<<1, 32>>>(ei);
    k_init<<<(NN + 255) / 256, 256>>>();
    k_count<<<(EE + 255) / 256, 256>>>(ei);
    k_dinv<<<(NN + 255) / 256, 256>>>();
    k_scan1<<<nb, 256>>>();
    k_scan2<<<1, 32>>>(nb);
    k_scan3<<<(NN + 255) / 256, 256>>>();
    k_fill<<<(EE + 255) / 256, 256>>>(ei);

    // layer 1: h = X @ W1 ; x = relu(agg(h) + b1)
    k_gemm<<<NN / 32, 256>>>(X, 0, W1);
    k_agg<<<NN / 8, 256>>>(b1);
    // layer 2: h = x @ W2 ; x = relu(agg(h) + b2)
    k_gemm<<<NN / 32, 256>>>(X, 1, W2);
    k_agg<<<NN / 8, 256>>>(b2);

    // pooling + fc
    k_pool<<<(NN + 511) / 512, 128>>>();
    k_fc<<<1, 256>>>(fcW, fcb, out);
}